// round 1
// baseline (speedup 1.0000x reference)
#include <cuda_runtime.h>
#include <math.h>

// Problem constants
#define B_   2
#define S_   2048
#define D_   2048
#define H_   16
#define HD_  128
#define M_   (B_ * S_)     // 4096 rows (b,s)
#define F_   (H_ * HD_)    // 2048
#define NQKV (3 * F_)      // 6144

// Scratch (device globals; no allocation allowed)
__device__ float g_Q[(size_t)B_ * H_ * S_ * HD_];
__device__ float g_K[(size_t)B_ * H_ * S_ * HD_];
__device__ float g_V[(size_t)B_ * H_ * S_ * HD_];
__device__ float g_attn[(size_t)B_ * S_ * F_];

// ---------------------------------------------------------------------------
// Kernel 1: QKV projection (A[4096,2048] x W[6144,2048]^T) with fused RoPE.
// 128x128 tile, BK=16, 256 threads, 8x8 per-thread (4+4 split rows/cols).
// N-tiles (width 128) align exactly with q/k/v sub-blocks of one head
// (per-head stride 384 = 3*128). Split-column layout (c, c+64) gives each
// thread the rotate-half pair in registers.
// ---------------------------------------------------------------------------
__global__ void __launch_bounds__(256, 2) qkv_rope_kernel(
    const float* __restrict__ A, const float* __restrict__ W,
    const float* __restrict__ cs, const float* __restrict__ sn)
{
    __shared__ float As[16][128];
    __shared__ float Bs[16][128];
    const int tid = threadIdx.x;
    const int tx = tid & 15, ty = tid >> 4;
    const int m0 = blockIdx.y << 7, n0 = blockIdx.x << 7;
    const int lr = tid >> 2;            // 0..63
    const int lc = (tid & 3) << 2;      // 0,4,8,12

    float acc[8][8];
#pragma unroll
    for (int i = 0; i < 8; i++)
#pragma unroll
        for (int j = 0; j < 8; j++) acc[i][j] = 0.f;

    const float* Ap0 = A + (size_t)(m0 + lr) * D_ + lc;
    const float* Ap1 = Ap0 + (size_t)64 * D_;
    const float* Wp0 = W + (size_t)(n0 + lr) * D_ + lc;
    const float* Wp1 = Wp0 + (size_t)64 * D_;

    for (int k0 = 0; k0 < D_; k0 += 16) {
        float4 a0 = *(const float4*)(Ap0 + k0);
        float4 a1 = *(const float4*)(Ap1 + k0);
        float4 b0 = *(const float4*)(Wp0 + k0);
        float4 b1 = *(const float4*)(Wp1 + k0);
        __syncthreads();
        As[lc + 0][lr] = a0.x; As[lc + 1][lr] = a0.y; As[lc + 2][lr] = a0.z; As[lc + 3][lr] = a0.w;
        As[lc + 0][lr + 64] = a1.x; As[lc + 1][lr + 64] = a1.y; As[lc + 2][lr + 64] = a1.z; As[lc + 3][lr + 64] = a1.w;
        Bs[lc + 0][lr] = b0.x; Bs[lc + 1][lr] = b0.y; Bs[lc + 2][lr] = b0.z; Bs[lc + 3][lr] = b0.w;
        Bs[lc + 0][lr + 64] = b1.x; Bs[lc + 1][lr + 64] = b1.y; Bs[lc + 2][lr + 64] = b1.z; Bs[lc + 3][lr + 64] = b1.w;
        __syncthreads();
#pragma unroll
        for (int kk = 0; kk < 16; kk++) {
            float ar[8], br[8];
            *(float4*)&ar[0] = *(const float4*)&As[kk][ty << 2];
            *(float4*)&ar[4] = *(const float4*)&As[kk][(ty << 2) + 64];
            *(float4*)&br[0] = *(const float4*)&Bs[kk][tx << 2];
            *(float4*)&br[4] = *(const float4*)&Bs[kk][(tx << 2) + 64];
#pragma unroll
            for (int i = 0; i < 8; i++)
#pragma unroll
                for (int j = 0; j < 8; j++) acc[i][j] = fmaf(ar[i], br[j], acc[i][j]);
        }
    }

    // Epilogue: scatter to Q/K/V in [B,H,S,HD] with RoPE on q,k.
    const int h   = n0 / 384;
    const int sub = (n0 % 384) >> 7;   // 0=q, 1=k, 2=v
    float* dst = (sub == 0) ? g_Q : (sub == 1 ? g_K : g_V);
#pragma unroll
    for (int i = 0; i < 8; i++) {
        const int rl = (i < 4) ? ((ty << 2) + i) : (64 + (ty << 2) + i - 4);
        const int m = m0 + rl;
        const int b = m / S_, s = m % S_;
        float* orow = dst + ((size_t)(b * H_ + h) * S_ + s) * HD_;
        if (sub == 2) {
#pragma unroll
            for (int j = 0; j < 8; j++) {
                const int cl = (j < 4) ? ((tx << 2) + j) : (64 + (tx << 2) + j - 4);
                orow[cl] = acc[i][j];
            }
        } else {
            const float* crow = cs + (size_t)s * HD_;
            const float* srow = sn + (size_t)s * HD_;
#pragma unroll
            for (int j = 0; j < 4; j++) {
                const int cA = (tx << 2) + j;
                const int cB = cA + 64;
                const float xa = acc[i][j];
                const float xb = acc[i][j + 4];
                orow[cA] = xa * crow[cA] - xb * srow[cA];   // e < 64: x*cos - x[e+64]*sin
                orow[cB] = xb * crow[cB] + xa * srow[cB];   // e >=64: x*cos + x[e-64]*sin
            }
        }
    }
}

// ---------------------------------------------------------------------------
// Kernel 2: causal flash attention, fp32, 64(q) x 64(k) tiles.
// Grid: (S/64, H, B). Block: 256 threads (16x16). Each thread: 4 rows x 8 cols
// of the output accumulator; 4x4 of the score tile.
// ---------------------------------------------------------------------------
#define KPAD 132          // K tile row stride (floats), float4-aligned, conflict-light
#define SPAD 65           // score tile row stride
#define ATTN_SMEM_FLOATS (64*128 + 64*KPAD + 64*128 + 64*SPAD + 3*64)
#define ATTN_SMEM_BYTES  (ATTN_SMEM_FLOATS * 4)

__global__ void __launch_bounds__(256, 1) attn_kernel()
{
    extern __shared__ float sm[];
    float* Qs   = sm;                    // 64*128
    float* Ks   = Qs + 64 * 128;         // 64*KPAD
    float* Vs   = Ks + 64 * KPAD;        // 64*128
    float* Ss   = Vs + 64 * 128;         // 64*SPAD
    float* mrow = Ss + 64 * SPAD;        // 64
    float* lrow = mrow + 64;             // 64
    float* arow = lrow + 64;             // 64

    const int tid = threadIdx.x;
    const int tx = tid & 15, ty = tid >> 4;
    const int qt = blockIdx.x, h = blockIdx.y, b = blockIdx.z;
    const size_t base = (size_t)(b * H_ + h) * S_ * HD_;
    const int qg0 = qt << 6;
    const float scale = 0.08838834764831845f;  // 1/sqrt(128)

    // Load Q tile (64x128), coalesced float4
#pragma unroll
    for (int i = 0; i < 8; i++) {
        const int idx4 = i * 256 + tid;          // 0..2047
        const int row = idx4 >> 5, c4 = idx4 & 31;
        float4 v = *(const float4*)(g_Q + base + (size_t)(qg0 + row) * HD_ + (c4 << 2));
        *(float4*)(Qs + row * 128 + (c4 << 2)) = v;
    }
    if (tid < 64) { mrow[tid] = -1e30f; lrow[tid] = 0.f; }

    float o[4][8];
#pragma unroll
    for (int i = 0; i < 4; i++)
#pragma unroll
        for (int j = 0; j < 8; j++) o[i][j] = 0.f;

    __syncthreads();

    for (int kt = 0; kt <= qt; kt++) {
        const int kg0 = kt << 6;
        // Load K (padded stride) and V tiles
#pragma unroll
        for (int i = 0; i < 8; i++) {
            const int idx4 = i * 256 + tid;
            const int row = idx4 >> 5, c4 = idx4 & 31;
            const size_t goff = base + (size_t)(kg0 + row) * HD_ + (c4 << 2);
            float4 kv = *(const float4*)(g_K + goff);
            *(float4*)(Ks + row * KPAD + (c4 << 2)) = kv;
            float4 vv = *(const float4*)(g_V + goff);
            *(float4*)(Vs + row * 128 + (c4 << 2)) = vv;
        }
        __syncthreads();

        // Scores: 4x4 per thread, dot over 128 (vectorized float4 over e)
        float sc[4][4];
#pragma unroll
        for (int i = 0; i < 4; i++)
#pragma unroll
            for (int j = 0; j < 4; j++) sc[i][j] = 0.f;

        for (int e4 = 0; e4 < 128; e4 += 4) {
            float4 q[4], k[4];
#pragma unroll
            for (int i = 0; i < 4; i++)
                q[i] = *(const float4*)(Qs + ((ty << 2) + i) * 128 + e4);
#pragma unroll
            for (int j = 0; j < 4; j++)
                k[j] = *(const float4*)(Ks + ((tx << 2) + j) * KPAD + e4);
#pragma unroll
            for (int i = 0; i < 4; i++)
#pragma unroll
                for (int j = 0; j < 4; j++) {
                    sc[i][j] = fmaf(q[i].x, k[j].x, sc[i][j]);
                    sc[i][j] = fmaf(q[i].y, k[j].y, sc[i][j]);
                    sc[i][j] = fmaf(q[i].z, k[j].z, sc[i][j]);
                    sc[i][j] = fmaf(q[i].w, k[j].w, sc[i][j]);
                }
        }

        // Mask (diagonal tile only), scale, store to Ss
        const bool diag = (kt == qt);
#pragma unroll
        for (int i = 0; i < 4; i++)
#pragma unroll
            for (int j = 0; j < 4; j++) {
                float v = sc[i][j] * scale;
                if (diag && ((kg0 + (tx << 2) + j) > (qg0 + (ty << 2) + i))) v = -1e30f;
                Ss[((ty << 2) + i) * SPAD + (tx << 2) + j] = v;
            }
        __syncthreads();

        // Online softmax row pass: one thread per row (tid < 64)
        if (tid < 64) {
            const int r = tid;
            const float mold = mrow[r];
            float mx = mold;
#pragma unroll 8
            for (int c = 0; c < 64; c++) mx = fmaxf(mx, Ss[r * SPAD + c]);
            const float al = __expf(mold - mx);
            float sum = 0.f;
#pragma unroll 8
            for (int c = 0; c < 64; c++) {
                const float p = __expf(Ss[r * SPAD + c] - mx);
                Ss[r * SPAD + c] = p;
                sum += p;
            }
            mrow[r] = mx;
            lrow[r] = lrow[r] * al + sum;
            arow[r] = al;
        }
        __syncthreads();

        // Rescale accumulator, then O += P @ V
#pragma unroll
        for (int i = 0; i < 4; i++) {
            const float al = arow[(ty << 2) + i];
#pragma unroll
            for (int j = 0; j < 8; j++) o[i][j] *= al;
        }
#pragma unroll 2
        for (int c = 0; c < 64; c++) {
            float4 v0 = *(const float4*)(Vs + c * 128 + (tx << 3));
            float4 v1 = *(const float4*)(Vs + c * 128 + (tx << 3) + 4);
#pragma unroll
            for (int i = 0; i < 4; i++) {
                const float p = Ss[((ty << 2) + i) * SPAD + c];
                o[i][0] = fmaf(p, v0.x, o[i][0]);
                o[i][1] = fmaf(p, v0.y, o[i][1]);
                o[i][2] = fmaf(p, v0.z, o[i][2]);
                o[i][3] = fmaf(p, v0.w, o[i][3]);
                o[i][4] = fmaf(p, v1.x, o[i][4]);
                o[i][5] = fmaf(p, v1.y, o[i][5]);
                o[i][6] = fmaf(p, v1.z, o[i][6]);
                o[i][7] = fmaf(p, v1.w, o[i][7]);
            }
        }
        __syncthreads();   // before next iteration overwrites K/V/S
    }

    // Epilogue: normalize and store to g_attn [B,S,H*HD]
#pragma unroll
    for (int i = 0; i < 4; i++) {
        const int r = (ty << 2) + i;
        const float inv = 1.0f / lrow[r];
        const int s = qg0 + r;
        float* orow = g_attn + ((size_t)b * S_ + s) * F_ + h * HD_ + (tx << 3);
        float4 w0 = make_float4(o[i][0] * inv, o[i][1] * inv, o[i][2] * inv, o[i][3] * inv);
        float4 w1 = make_float4(o[i][4] * inv, o[i][5] * inv, o[i][6] * inv, o[i][7] * inv);
        *(float4*)(orow) = w0;
        *(float4*)(orow + 4) = w1;
    }
}

// ---------------------------------------------------------------------------
// Kernel 3: output projection  out[m,d] = sum_f attn[m,f] * w_o[d,f]
// Same SGEMM skeleton as kernel 1.
// ---------------------------------------------------------------------------
__global__ void __launch_bounds__(256, 2) out_proj_kernel(
    const float* __restrict__ Wo, float* __restrict__ out)
{
    __shared__ float As[16][128];
    __shared__ float Bs[16][128];
    const int tid = threadIdx.x;
    const int tx = tid & 15, ty = tid >> 4;
    const int m0 = blockIdx.y << 7, n0 = blockIdx.x << 7;
    const int lr = tid >> 2;
    const int lc = (tid & 3) << 2;

    float acc[8][8];
#pragma unroll
    for (int i = 0; i < 8; i++)
#pragma unroll
        for (int j = 0; j < 8; j++) acc[i][j] = 0.f;

    const float* Ap0 = g_attn + (size_t)(m0 + lr) * F_ + lc;
    const float* Ap1 = Ap0 + (size_t)64 * F_;
    const float* Wp0 = Wo + (size_t)(n0 + lr) * F_ + lc;
    const float* Wp1 = Wp0 + (size_t)64 * F_;

    for (int k0 = 0; k0 < F_; k0 += 16) {
        float4 a0 = *(const float4*)(Ap0 + k0);
        float4 a1 = *(const float4*)(Ap1 + k0);
        float4 b0 = *(const float4*)(Wp0 + k0);
        float4 b1 = *(const float4*)(Wp1 + k0);
        __syncthreads();
        As[lc + 0][lr] = a0.x; As[lc + 1][lr] = a0.y; As[lc + 2][lr] = a0.z; As[lc + 3][lr] = a0.w;
        As[lc + 0][lr + 64] = a1.x; As[lc + 1][lr + 64] = a1.y; As[lc + 2][lr + 64] = a1.z; As[lc + 3][lr + 64] = a1.w;
        Bs[lc + 0][lr] = b0.x; Bs[lc + 1][lr] = b0.y; Bs[lc + 2][lr] = b0.z; Bs[lc + 3][lr] = b0.w;
        Bs[lc + 0][lr + 64] = b1.x; Bs[lc + 1][lr + 64] = b1.y; Bs[lc + 2][lr + 64] = b1.z; Bs[lc + 3][lr + 64] = b1.w;
        __syncthreads();
#pragma unroll
        for (int kk = 0; kk < 16; kk++) {
            float ar[8], br[8];
            *(float4*)&ar[0] = *(const float4*)&As[kk][ty << 2];
            *(float4*)&ar[4] = *(const float4*)&As[kk][(ty << 2) + 64];
            *(float4*)&br[0] = *(const float4*)&Bs[kk][tx << 2];
            *(float4*)&br[4] = *(const float4*)&Bs[kk][(tx << 2) + 64];
#pragma unroll
            for (int i = 0; i < 8; i++)
#pragma unroll
                for (int j = 0; j < 8; j++) acc[i][j] = fmaf(ar[i], br[j], acc[i][j]);
        }
    }

#pragma unroll
    for (int i = 0; i < 8; i++) {
        const int rl = (i < 4) ? ((ty << 2) + i) : (64 + (ty << 2) + i - 4);
        float* orow = out + (size_t)(m0 + rl) * D_ + n0;
        float4 w0 = make_float4(acc[i][0], acc[i][1], acc[i][2], acc[i][3]);
        float4 w1 = make_float4(acc[i][4], acc[i][5], acc[i][6], acc[i][7]);
        *(float4*)(orow + (tx << 2)) = w0;
        *(float4*)(orow + (tx << 2) + 64) = w1;
    }
}

// ---------------------------------------------------------------------------
extern "C" void kernel_launch(void* const* d_in, const int* in_sizes, int n_in,
                              void* d_out, int out_size)
{
    const float* hs = (const float*)d_in[0];   // hidden_states [B,S,D]
    const float* cs = (const float*)d_in[1];   // cos [S,HD]
    const float* sn = (const float*)d_in[2];   // sin [S,HD]
    const float* wq = (const float*)d_in[3];   // w_qkv [3,H*HD,D] -> flat [6144,2048]
    const float* wo = (const float*)d_in[4];   // w_o [D, H*HD]
    float* out = (float*)d_out;

    cudaFuncSetAttribute(attn_kernel,
                         cudaFuncAttributeMaxDynamicSharedMemorySize,
                         ATTN_SMEM_BYTES);

    // 1. QKV projection + RoPE -> g_Q, g_K, g_V
    qkv_rope_kernel<<<dim3(NQKV / 128, M_ / 128), 256>>>(hs, wq, cs, sn);

    // 2. Causal flash attention -> g_attn
    attn_kernel<<<dim3(S_ / 64, H_, B_), 256, ATTN_SMEM_BYTES>>>();

    // 3. Output projection -> d_out
    out_proj_kernel<<<dim3(D_ / 128, M_ / 128), 256>>>(wo, out);
}

// round 2
// speedup vs baseline: 1.2121x; 1.2121x over previous
#include <cuda_runtime.h>
#include <math.h>

// Problem constants
#define B_   2
#define S_   2048
#define D_   2048
#define H_   16
#define HD_  128
#define M_   (B_ * S_)     // 4096 rows (b,s)
#define F_   (H_ * HD_)    // 2048
#define NQKV (3 * F_)      // 6144

typedef unsigned long long u64;

// ---- packed f32x2 helpers (B300: full-rate FFMA2, 2x fp32) ----
__device__ __forceinline__ u64 pack2(float lo, float hi) {
    u64 r; asm("mov.b64 %0, {%1, %2};" : "=l"(r) : "f"(lo), "f"(hi)); return r;
}
__device__ __forceinline__ float2 unpack2(u64 v) {
    float2 f; asm("mov.b64 {%0, %1}, %2;" : "=f"(f.x), "=f"(f.y) : "l"(v)); return f;
}
__device__ __forceinline__ u64 fma2(u64 a, u64 b, u64 c) {
    u64 d; asm("fma.rn.f32x2 %0, %1, %2, %3;" : "=l"(d) : "l"(a), "l"(b), "l"(c)); return d;
}
__device__ __forceinline__ u64 mul2(u64 a, u64 b) {
    u64 d; asm("mul.rn.f32x2 %0, %1, %2;" : "=l"(d) : "l"(a), "l"(b)); return d;
}

// Scratch (device globals; no allocation allowed)
__device__ float g_Q[(size_t)B_ * H_ * S_ * HD_];
__device__ float g_K[(size_t)B_ * H_ * S_ * HD_];
__device__ float g_V[(size_t)B_ * H_ * S_ * HD_];
__device__ float g_attn[(size_t)B_ * S_ * F_];

// ---------------------------------------------------------------------------
// Kernel 1: QKV projection with fused RoPE. 128x128 tile, BK=16, 256 thr,
// 8x8 per-thread, inner loop in packed f32x2 (acc pairs over columns).
// ---------------------------------------------------------------------------
__global__ void __launch_bounds__(256, 2) qkv_rope_kernel(
    const float* __restrict__ A, const float* __restrict__ W,
    const float* __restrict__ cs, const float* __restrict__ sn)
{
    __shared__ float As[16][128];
    __shared__ float Bs[16][128];
    const int tid = threadIdx.x;
    const int tx = tid & 15, ty = tid >> 4;
    const int m0 = blockIdx.y << 7, n0 = blockIdx.x << 7;
    const int lr = tid >> 2;            // 0..63
    const int lc = (tid & 3) << 2;      // 0,4,8,12

    u64 acc2[8][4];
    const u64 z = pack2(0.f, 0.f);
#pragma unroll
    for (int i = 0; i < 8; i++)
#pragma unroll
        for (int j = 0; j < 4; j++) acc2[i][j] = z;

    const float* Ap0 = A + (size_t)(m0 + lr) * D_ + lc;
    const float* Ap1 = Ap0 + (size_t)64 * D_;
    const float* Wp0 = W + (size_t)(n0 + lr) * D_ + lc;
    const float* Wp1 = Wp0 + (size_t)64 * D_;

    for (int k0 = 0; k0 < D_; k0 += 16) {
        float4 a0 = *(const float4*)(Ap0 + k0);
        float4 a1 = *(const float4*)(Ap1 + k0);
        float4 b0 = *(const float4*)(Wp0 + k0);
        float4 b1 = *(const float4*)(Wp1 + k0);
        __syncthreads();
        As[lc + 0][lr] = a0.x; As[lc + 1][lr] = a0.y; As[lc + 2][lr] = a0.z; As[lc + 3][lr] = a0.w;
        As[lc + 0][lr + 64] = a1.x; As[lc + 1][lr + 64] = a1.y; As[lc + 2][lr + 64] = a1.z; As[lc + 3][lr + 64] = a1.w;
        Bs[lc + 0][lr] = b0.x; Bs[lc + 1][lr] = b0.y; Bs[lc + 2][lr] = b0.z; Bs[lc + 3][lr] = b0.w;
        Bs[lc + 0][lr + 64] = b1.x; Bs[lc + 1][lr + 64] = b1.y; Bs[lc + 2][lr + 64] = b1.z; Bs[lc + 3][lr + 64] = b1.w;
        __syncthreads();
#pragma unroll
        for (int kk = 0; kk < 16; kk++) {
            ulonglong2 bl = *(const ulonglong2*)&Bs[kk][tx << 2];          // (b0,b1),(b2,b3)
            ulonglong2 bh = *(const ulonglong2*)&Bs[kk][(tx << 2) + 64];   // (b4,b5),(b6,b7)
            float4 a0r = *(const float4*)&As[kk][ty << 2];
            float4 a1r = *(const float4*)&As[kk][(ty << 2) + 64];
            float ar[8] = {a0r.x, a0r.y, a0r.z, a0r.w, a1r.x, a1r.y, a1r.z, a1r.w};
#pragma unroll
            for (int i = 0; i < 8; i++) {
                const u64 a2 = pack2(ar[i], ar[i]);
                acc2[i][0] = fma2(a2, bl.x, acc2[i][0]);
                acc2[i][1] = fma2(a2, bl.y, acc2[i][1]);
                acc2[i][2] = fma2(a2, bh.x, acc2[i][2]);
                acc2[i][3] = fma2(a2, bh.y, acc2[i][3]);
            }
        }
    }

    // Unpack
    float acc[8][8];
#pragma unroll
    for (int i = 0; i < 8; i++) {
        float2 p0 = unpack2(acc2[i][0]), p1 = unpack2(acc2[i][1]);
        float2 p2 = unpack2(acc2[i][2]), p3 = unpack2(acc2[i][3]);
        acc[i][0] = p0.x; acc[i][1] = p0.y; acc[i][2] = p1.x; acc[i][3] = p1.y;
        acc[i][4] = p2.x; acc[i][5] = p2.y; acc[i][6] = p3.x; acc[i][7] = p3.y;
    }

    // Epilogue: scatter to Q/K/V in [B,H,S,HD] with RoPE on q,k.
    const int h   = n0 / 384;
    const int sub = (n0 % 384) >> 7;   // 0=q, 1=k, 2=v
    float* dst = (sub == 0) ? g_Q : (sub == 1 ? g_K : g_V);
#pragma unroll
    for (int i = 0; i < 8; i++) {
        const int rl = (i < 4) ? ((ty << 2) + i) : (64 + (ty << 2) + i - 4);
        const int m = m0 + rl;
        const int b = m / S_, s = m % S_;
        float* orow = dst + ((size_t)(b * H_ + h) * S_ + s) * HD_;
        if (sub == 2) {
#pragma unroll
            for (int j = 0; j < 8; j++) {
                const int cl = (j < 4) ? ((tx << 2) + j) : (64 + (tx << 2) + j - 4);
                orow[cl] = acc[i][j];
            }
        } else {
            const float* crow = cs + (size_t)s * HD_;
            const float* srow = sn + (size_t)s * HD_;
#pragma unroll
            for (int j = 0; j < 4; j++) {
                const int cA = (tx << 2) + j;
                const int cB = cA + 64;
                const float xa = acc[i][j];
                const float xb = acc[i][j + 4];
                orow[cA] = xa * crow[cA] - xb * srow[cA];
                orow[cB] = xb * crow[cB] + xa * srow[cB];
            }
        }
    }
}

// ---------------------------------------------------------------------------
// Kernel 2: causal flash attention, fp32->f32x2, 64(q) x 64(k) tiles.
// Block 256 threads (16x16). Scores packed over reduction dim (e).
// Online softmax fully in registers + shfl reductions (no serial row pass).
// K tile XOR-swizzled (conflict-free LDS.128).
// ---------------------------------------------------------------------------
#define SPAD 65
#define ATTN_SMEM_FLOATS (64*128 + 64*128 + 64*128 + 64*SPAD)
#define ATTN_SMEM_BYTES  (ATTN_SMEM_FLOATS * 4)

__global__ void __launch_bounds__(256, 1) attn_kernel()
{
    extern __shared__ float sm[];
    float* Qs = sm;                    // 64*128
    float* Ks = Qs + 64 * 128;         // 64*128, chunk-swizzled
    float* Vs = Ks + 64 * 128;         // 64*128
    float* Ss = Vs + 64 * 128;         // 64*SPAD

    const int tid = threadIdx.x;
    const int tx = tid & 15, ty = tid >> 4;
    const int qt = blockIdx.x, h = blockIdx.y, b = blockIdx.z;
    const size_t base = (size_t)(b * H_ + h) * S_ * HD_;
    const int qg0 = qt << 6;
    const float scale = 0.08838834764831845f;  // 1/sqrt(128)

    // Load Q tile (64x128)
#pragma unroll
    for (int i = 0; i < 8; i++) {
        const int idx4 = i * 256 + tid;
        const int row = idx4 >> 5, c4 = idx4 & 31;
        float4 v = *(const float4*)(g_Q + base + (size_t)(qg0 + row) * HD_ + (c4 << 2));
        *(float4*)(Qs + row * 128 + (c4 << 2)) = v;
    }

    float mrun[4], lrun[4];
#pragma unroll
    for (int i = 0; i < 4; i++) { mrun[i] = -1e30f; lrun[i] = 0.f; }

    u64 o2[4][4];
    const u64 z = pack2(0.f, 0.f);
#pragma unroll
    for (int i = 0; i < 4; i++)
#pragma unroll
        for (int j = 0; j < 4; j++) o2[i][j] = z;

    __syncthreads();

    for (int kt = 0; kt <= qt; kt++) {
        const int kg0 = kt << 6;
        // Load K (swizzled chunks) and V tiles
#pragma unroll
        for (int i = 0; i < 8; i++) {
            const int idx4 = i * 256 + tid;
            const int row = idx4 >> 5, c4 = idx4 & 31;
            const size_t goff = base + (size_t)(kg0 + row) * HD_ + (c4 << 2);
            float4 kv = *(const float4*)(g_K + goff);
            const int kc4 = c4 ^ ((row >> 2) & 7);
            *(float4*)(Ks + row * 128 + (kc4 << 2)) = kv;
            float4 vv = *(const float4*)(g_V + goff);
            *(float4*)(Vs + row * 128 + (c4 << 2)) = vv;
        }
        __syncthreads();

        // Scores: 4x4 per thread; packed over reduction dim e.
        u64 sc2[4][4];
#pragma unroll
        for (int i = 0; i < 4; i++)
#pragma unroll
            for (int j = 0; j < 4; j++) sc2[i][j] = z;

        const int ksw = tx & 7;   // (key>>2)&7 for key = tx*4+j (j<4)
        for (int e4 = 0; e4 < 128; e4 += 4) {
            ulonglong2 q[4], k[4];
#pragma unroll
            for (int i = 0; i < 4; i++)
                q[i] = *(const ulonglong2*)(Qs + ((ty << 2) + i) * 128 + e4);
            const int kc = (((e4 >> 2) ^ ksw) << 2);
#pragma unroll
            for (int j = 0; j < 4; j++)
                k[j] = *(const ulonglong2*)(Ks + ((tx << 2) + j) * 128 + kc);
#pragma unroll
            for (int i = 0; i < 4; i++)
#pragma unroll
                for (int j = 0; j < 4; j++) {
                    sc2[i][j] = fma2(q[i].x, k[j].x, sc2[i][j]);
                    sc2[i][j] = fma2(q[i].y, k[j].y, sc2[i][j]);
                }
        }

        // Horizontal add, scale, mask
        float sc[4][4];
        const bool diag = (kt == qt);
#pragma unroll
        for (int i = 0; i < 4; i++)
#pragma unroll
            for (int j = 0; j < 4; j++) {
                float2 p = unpack2(sc2[i][j]);
                float v = (p.x + p.y) * scale;
                if (diag && ((kg0 + (tx << 2) + j) > (qg0 + (ty << 2) + i))) v = -1e30f;
                sc[i][j] = v;
            }

        // Online softmax in registers: row reductions across 16 tx lanes.
        float alpha[4];
#pragma unroll
        for (int i = 0; i < 4; i++) {
            float mx = fmaxf(fmaxf(sc[i][0], sc[i][1]), fmaxf(sc[i][2], sc[i][3]));
#pragma unroll
            for (int off = 8; off >= 1; off >>= 1)
                mx = fmaxf(mx, __shfl_xor_sync(0xffffffffu, mx, off));
            const float mnew = fmaxf(mrun[i], mx);
            alpha[i] = __expf(mrun[i] - mnew);
            float s0 = 0.f;
#pragma unroll
            for (int j = 0; j < 4; j++) {
                const float p = __expf(sc[i][j] - mnew);
                sc[i][j] = p;
                s0 += p;
            }
#pragma unroll
            for (int off = 8; off >= 1; off >>= 1)
                s0 += __shfl_xor_sync(0xffffffffu, s0, off);
            lrun[i] = lrun[i] * alpha[i] + s0;
            mrun[i] = mnew;
            // write p tile for the PV pass
#pragma unroll
            for (int j = 0; j < 4; j++)
                Ss[((ty << 2) + i) * SPAD + (tx << 2) + j] = sc[i][j];
        }
        __syncthreads();

        // Rescale accumulator, then O += P @ V (packed over column pairs)
#pragma unroll
        for (int i = 0; i < 4; i++) {
            const u64 al2 = pack2(alpha[i], alpha[i]);
#pragma unroll
            for (int j = 0; j < 4; j++) o2[i][j] = mul2(o2[i][j], al2);
        }
#pragma unroll 2
        for (int c = 0; c < 64; c++) {
            ulonglong2 v0 = *(const ulonglong2*)(Vs + c * 128 + (tx << 3));
            ulonglong2 v1 = *(const ulonglong2*)(Vs + c * 128 + (tx << 3) + 4);
#pragma unroll
            for (int i = 0; i < 4; i++) {
                const float p = Ss[((ty << 2) + i) * SPAD + c];
                const u64 p2 = pack2(p, p);
                o2[i][0] = fma2(p2, v0.x, o2[i][0]);
                o2[i][1] = fma2(p2, v0.y, o2[i][1]);
                o2[i][2] = fma2(p2, v1.x, o2[i][2]);
                o2[i][3] = fma2(p2, v1.y, o2[i][3]);
            }
        }
        __syncthreads();   // before next iteration overwrites K/V/S
    }

    // Epilogue: normalize and store to g_attn [B,S,H*HD]
#pragma unroll
    for (int i = 0; i < 4; i++) {
        const int r = (ty << 2) + i;
        const float inv = 1.0f / lrun[i];
        const int s = qg0 + r;
        float* orow = g_attn + ((size_t)b * S_ + s) * F_ + h * HD_ + (tx << 3);
        float2 a0 = unpack2(o2[i][0]), a1 = unpack2(o2[i][1]);
        float2 a2 = unpack2(o2[i][2]), a3 = unpack2(o2[i][3]);
        float4 w0 = make_float4(a0.x * inv, a0.y * inv, a1.x * inv, a1.y * inv);
        float4 w1 = make_float4(a2.x * inv, a2.y * inv, a3.x * inv, a3.y * inv);
        *(float4*)(orow) = w0;
        *(float4*)(orow + 4) = w1;
    }
}

// ---------------------------------------------------------------------------
// Kernel 3: output projection  out[m,d] = sum_f attn[m,f] * w_o[d,f]
// ---------------------------------------------------------------------------
__global__ void __launch_bounds__(256, 2) out_proj_kernel(
    const float* __restrict__ Wo, float* __restrict__ out)
{
    __shared__ float As[16][128];
    __shared__ float Bs[16][128];
    const int tid = threadIdx.x;
    const int tx = tid & 15, ty = tid >> 4;
    const int m0 = blockIdx.y << 7, n0 = blockIdx.x << 7;
    const int lr = tid >> 2;
    const int lc = (tid & 3) << 2;

    u64 acc2[8][4];
    const u64 z = pack2(0.f, 0.f);
#pragma unroll
    for (int i = 0; i < 8; i++)
#pragma unroll
        for (int j = 0; j < 4; j++) acc2[i][j] = z;

    const float* Ap0 = g_attn + (size_t)(m0 + lr) * F_ + lc;
    const float* Ap1 = Ap0 + (size_t)64 * F_;
    const float* Wp0 = Wo + (size_t)(n0 + lr) * F_ + lc;
    const float* Wp1 = Wp0 + (size_t)64 * F_;

    for (int k0 = 0; k0 < F_; k0 += 16) {
        float4 a0 = *(const float4*)(Ap0 + k0);
        float4 a1 = *(const float4*)(Ap1 + k0);
        float4 b0 = *(const float4*)(Wp0 + k0);
        float4 b1 = *(const float4*)(Wp1 + k0);
        __syncthreads();
        As[lc + 0][lr] = a0.x; As[lc + 1][lr] = a0.y; As[lc + 2][lr] = a0.z; As[lc + 3][lr] = a0.w;
        As[lc + 0][lr + 64] = a1.x; As[lc + 1][lr + 64] = a1.y; As[lc + 2][lr + 64] = a1.z; As[lc + 3][lr + 64] = a1.w;
        Bs[lc + 0][lr] = b0.x; Bs[lc + 1][lr] = b0.y; Bs[lc + 2][lr] = b0.z; Bs[lc + 3][lr] = b0.w;
        Bs[lc + 0][lr + 64] = b1.x; Bs[lc + 1][lr + 64] = b1.y; Bs[lc + 2][lr + 64] = b1.z; Bs[lc + 3][lr + 64] = b1.w;
        __syncthreads();
#pragma unroll
        for (int kk = 0; kk < 16; kk++) {
            ulonglong2 bl = *(const ulonglong2*)&Bs[kk][tx << 2];
            ulonglong2 bh = *(const ulonglong2*)&Bs[kk][(tx << 2) + 64];
            float4 a0r = *(const float4*)&As[kk][ty << 2];
            float4 a1r = *(const float4*)&As[kk][(ty << 2) + 64];
            float ar[8] = {a0r.x, a0r.y, a0r.z, a0r.w, a1r.x, a1r.y, a1r.z, a1r.w};
#pragma unroll
            for (int i = 0; i < 8; i++) {
                const u64 a2 = pack2(ar[i], ar[i]);
                acc2[i][0] = fma2(a2, bl.x, acc2[i][0]);
                acc2[i][1] = fma2(a2, bl.y, acc2[i][1]);
                acc2[i][2] = fma2(a2, bh.x, acc2[i][2]);
                acc2[i][3] = fma2(a2, bh.y, acc2[i][3]);
            }
        }
    }

#pragma unroll
    for (int i = 0; i < 8; i++) {
        const int rl = (i < 4) ? ((ty << 2) + i) : (64 + (ty << 2) + i - 4);
        float* orow = out + (size_t)(m0 + rl) * D_ + n0;
        float2 p0 = unpack2(acc2[i][0]), p1 = unpack2(acc2[i][1]);
        float2 p2 = unpack2(acc2[i][2]), p3 = unpack2(acc2[i][3]);
        float4 w0 = make_float4(p0.x, p0.y, p1.x, p1.y);
        float4 w1 = make_float4(p2.x, p2.y, p3.x, p3.y);
        *(float4*)(orow + (tx << 2)) = w0;
        *(float4*)(orow + (tx << 2) + 64) = w1;
    }
}

// ---------------------------------------------------------------------------
extern "C" void kernel_launch(void* const* d_in, const int* in_sizes, int n_in,
                              void* d_out, int out_size)
{
    const float* hs = (const float*)d_in[0];   // hidden_states [B,S,D]
    const float* cs = (const float*)d_in[1];   // cos [S,HD]
    const float* sn = (const float*)d_in[2];   // sin [S,HD]
    const float* wq = (const float*)d_in[3];   // w_qkv [3,H*HD,D] -> flat [6144,2048]
    const float* wo = (const float*)d_in[4];   // w_o [D, H*HD]
    float* out = (float*)d_out;

    cudaFuncSetAttribute(attn_kernel,
                         cudaFuncAttributeMaxDynamicSharedMemorySize,
                         ATTN_SMEM_BYTES);

    qkv_rope_kernel<<<dim3(NQKV / 128, M_ / 128), 256>>>(hs, wq, cs, sn);
    attn_kernel<<<dim3(S_ / 64, H_, B_), 256, ATTN_SMEM_BYTES>>>();
    out_proj_kernel<<<dim3(D_ / 128, M_ / 128), 256>>>(wo, out);
}

// round 4
// speedup vs baseline: 2.2124x; 1.8253x over previous
#include <cuda_runtime.h>
#include <cuda_bf16.h>
#include <cstdint>
#include <math.h>

// Problem constants
#define B_   2
#define S_   2048
#define D_   2048
#define H_   16
#define HD_  128
#define M_   (B_ * S_)     // 4096
#define F_   (H_ * HD_)    // 2048
#define NQKV (3 * F_)      // 6144

typedef unsigned long long u64;
typedef unsigned int u32;

// ---- packed f32x2 helpers (attention kernel) ----
__device__ __forceinline__ u64 pack2(float lo, float hi) {
    u64 r; asm("mov.b64 %0, {%1, %2};" : "=l"(r) : "f"(lo), "f"(hi)); return r;
}
__device__ __forceinline__ float2 unpack2(u64 v) {
    float2 f; asm("mov.b64 {%0, %1}, %2;" : "=f"(f.x), "=f"(f.y) : "l"(v)); return f;
}
__device__ __forceinline__ u64 fma2(u64 a, u64 b, u64 c) {
    u64 d; asm("fma.rn.f32x2 %0, %1, %2, %3;" : "=l"(d) : "l"(a), "l"(b), "l"(c)); return d;
}
__device__ __forceinline__ u64 mul2(u64 a, u64 b) {
    u64 d; asm("mul.rn.f32x2 %0, %1, %2;" : "=l"(d) : "l"(a), "l"(b)); return d;
}

__device__ __forceinline__ u32 smem_u32(const void* p) {
    u32 a; asm("{ .reg .u64 t; cvta.to.shared.u64 t, %1; cvt.u32.u64 %0, t; }" : "=r"(a) : "l"(p));
    return a;
}

// ---- mma.sync / ldmatrix / cp.async (standard PTX, no arch suffix needed) ----
__device__ __forceinline__ void ldsm4(u32* r, u32 addr) {
    asm volatile("ldmatrix.sync.aligned.m8n8.x4.shared.b16 {%0,%1,%2,%3}, [%4];"
        : "=r"(r[0]), "=r"(r[1]), "=r"(r[2]), "=r"(r[3]) : "r"(addr));
}
__device__ __forceinline__ void mma16816(float* d, const u32* a, const u32* b) {
    asm volatile("mma.sync.aligned.m16n8k16.row.col.f32.bf16.bf16.f32 "
        "{%0,%1,%2,%3}, {%4,%5,%6,%7}, {%8,%9}, {%0,%1,%2,%3};"
        : "+f"(d[0]), "+f"(d[1]), "+f"(d[2]), "+f"(d[3])
        : "r"(a[0]), "r"(a[1]), "r"(a[2]), "r"(a[3]), "r"(b[0]), "r"(b[1]));
}
__device__ __forceinline__ void cp_async16(u32 dst, const void* src) {
    asm volatile("cp.async.cg.shared.global [%0], [%1], 16;" :: "r"(dst), "l"(src));
}
#define CP_COMMIT() asm volatile("cp.async.commit_group;" ::: "memory")
#define CP_WAIT0()  asm volatile("cp.async.wait_group 0;" ::: "memory")

// ---------------- device scratch ----------------
__device__ float g_Q[(size_t)B_ * H_ * S_ * HD_];
__device__ float g_K[(size_t)B_ * H_ * S_ * HD_];
__device__ float g_V[(size_t)B_ * H_ * S_ * HD_];
__device__ __nv_bfloat16 g_Ahi[(size_t)M_ * D_],   g_Alo[(size_t)M_ * D_];
__device__ __nv_bfloat16 g_Whi[(size_t)NQKV * D_], g_Wlo[(size_t)NQKV * D_];
__device__ __nv_bfloat16 g_Wohi[(size_t)D_ * F_],  g_Wolo[(size_t)D_ * F_];
__device__ __nv_bfloat16 g_AThi[(size_t)M_ * F_],  g_ATlo[(size_t)M_ * F_];

// ---------------------------------------------------------------------------
// Split fp32 -> bf16 (hi, lo)
// ---------------------------------------------------------------------------
__global__ void split_bf16_kernel(const float4* __restrict__ x,
                                  uint2* __restrict__ hi, uint2* __restrict__ lo, int n4)
{
    int i = blockIdx.x * blockDim.x + threadIdx.x;
    if (i >= n4) return;
    float4 v = x[i];
    __nv_bfloat16 h0 = __float2bfloat16(v.x), h1 = __float2bfloat16(v.y);
    __nv_bfloat16 h2 = __float2bfloat16(v.z), h3 = __float2bfloat16(v.w);
    __nv_bfloat16 l0 = __float2bfloat16(v.x - __bfloat162float(h0));
    __nv_bfloat16 l1 = __float2bfloat16(v.y - __bfloat162float(h1));
    __nv_bfloat16 l2 = __float2bfloat16(v.z - __bfloat162float(h2));
    __nv_bfloat16 l3 = __float2bfloat16(v.w - __bfloat162float(h3));
    uint2 ho, lw;
    ho.x = ((u32)__bfloat16_as_ushort(h1) << 16) | __bfloat16_as_ushort(h0);
    ho.y = ((u32)__bfloat16_as_ushort(h3) << 16) | __bfloat16_as_ushort(h2);
    lw.x = ((u32)__bfloat16_as_ushort(l1) << 16) | __bfloat16_as_ushort(l0);
    lw.y = ((u32)__bfloat16_as_ushort(l3) << 16) | __bfloat16_as_ushort(l2);
    hi[i] = ho; lo[i] = lw;
}

// ---------------------------------------------------------------------------
// bf16x3 GEMM via mma.sync m16n8k16. Tile 128x128, K=2048 in 32 chunks of 64.
// 8 warps: warp grid 2(m) x 4(n), 64x32 per warp; acc 4x4 frags.
// Smem: 2 stages x [Ahi|Alo|Bhi|Blo] x 16KB (rows of 64 bf16 = 128B, XOR-swizzled).
// MODE 0: QKV + RoPE -> g_Q/g_K/g_V.  MODE 1: out proj -> out.
// ---------------------------------------------------------------------------
#define NCHUNK 32
#define TILEB 16384
#define STAGEB (4 * TILEB)
#define MMA_SMEM_BYTES (2 * STAGEB)    // 128KB; epilogue reuses 67.6KB of it

__device__ __forceinline__ u32 swz(u32 row, u32 cb) {   // row*128 + swizzled col byte
    return row * 128u + (cb ^ ((row & 7u) << 4));
}

template <int MODE>
__global__ void __launch_bounds__(256, 1) mma_gemm_kernel(
    const __nv_bfloat16* __restrict__ Ahi, const __nv_bfloat16* __restrict__ Alo,
    const __nv_bfloat16* __restrict__ Bhi, const __nv_bfloat16* __restrict__ Blo,
    const float* __restrict__ cs, const float* __restrict__ sn,
    float* __restrict__ out)
{
    extern __shared__ char dyn_smem[];
    const u32 smb = smem_u32(dyn_smem);

    const int tid = threadIdx.x;
    const int wid = tid >> 5;
    const int lane = tid & 31;
    const int wm = wid >> 2, wn = wid & 3;
    const int m0 = blockIdx.y << 7;
    const int n0 = blockIdx.x << 7;

    // cp.async coordinates: per operand 1024 x 16B; lin = rep*256+tid
    const int cprow = tid >> 1;                 // rows: (rep*256+tid)>>3 pattern below
    (void)cprow;

    const __nv_bfloat16* srcOp[4] = {Ahi, Alo, Bhi, Blo};
    const int rowOff[4] = {m0, m0, n0, n0};

    // ---- issue chunk 0 ----
    {
#pragma unroll
        for (int op = 0; op < 4; op++) {
#pragma unroll
            for (int rep = 0; rep < 4; rep++) {
                int lin = rep * 256 + tid;
                int row = lin >> 3, u = lin & 7;
                cp_async16(smb + op * TILEB + swz(row, u * 16),
                           srcOp[op] + (size_t)(rowOff[op] + row) * 2048 + u * 8);
            }
        }
        CP_COMMIT(); CP_WAIT0();
    }
    __syncthreads();

    // fragment address precompute
    const u32 aRow = (u32)(wm * 64 + (lane & 15));
    const u32 aSw = (aRow & 7u) << 4;
    const u32 aColSel = (u32)((lane >> 4) << 4);       // 0 / 16
    u32 aOff[4];
#pragma unroll
    for (int fm = 0; fm < 4; fm++) aOff[fm] = (aRow + fm * 16) * 128u;

    u32 bOff[2], bSw[2];
#pragma unroll
    for (int p = 0; p < 2; p++) {
        u32 brow = (u32)(wn * 32 + p * 16 + ((lane >> 4) << 3) + (lane & 7));
        bOff[p] = brow * 128u;
        bSw[p] = (brow & 7u) << 4;
    }
    const u32 bColSel = (u32)(((lane >> 3) & 1) << 4);

    float acc[4][4][4];
#pragma unroll
    for (int i = 0; i < 4; i++)
#pragma unroll
        for (int j = 0; j < 4; j++)
#pragma unroll
            for (int q = 0; q < 4; q++) acc[i][j][q] = 0.f;

    for (int c = 0; c < NCHUNK; c++) {
        const u32 stage = smb + (u32)(c & 1) * STAGEB;
        // issue next chunk into other stage
        if (c + 1 < NCHUNK) {
            const int k0 = (c + 1) * 64;
            const u32 nst = smb + (u32)((c + 1) & 1) * STAGEB;
#pragma unroll
            for (int op = 0; op < 4; op++) {
#pragma unroll
                for (int rep = 0; rep < 4; rep++) {
                    int lin = rep * 256 + tid;
                    int row = lin >> 3, u = lin & 7;
                    cp_async16(nst + op * TILEB + swz(row, u * 16),
                               srcOp[op] + (size_t)(rowOff[op] + row) * 2048 + k0 + u * 8);
                }
            }
            CP_COMMIT();
        }
        // compute current stage: 4 ksteps of 16
#pragma unroll
        for (int ks = 0; ks < 4; ks++) {
            const u32 cbA = (u32)(ks * 32) + aColSel;
            const u32 cbB = (u32)(ks * 32) + bColSel;
            u32 ah[4][4], al[4][4];
#pragma unroll
            for (int fm = 0; fm < 4; fm++) {
                ldsm4(ah[fm], stage + aOff[fm] + (cbA ^ aSw));
                ldsm4(al[fm], stage + TILEB + aOff[fm] + (cbA ^ aSw));
            }
            u32 bh[2][4], bl[2][4];
#pragma unroll
            for (int p = 0; p < 2; p++) {
                ldsm4(bh[p], stage + 2 * TILEB + bOff[p] + (cbB ^ bSw[p]));
                ldsm4(bl[p], stage + 3 * TILEB + bOff[p] + (cbB ^ bSw[p]));
            }
#pragma unroll
            for (int fm = 0; fm < 4; fm++)
#pragma unroll
                for (int p = 0; p < 2; p++)
#pragma unroll
                    for (int q = 0; q < 2; q++) {
                        float* d = acc[fm][p * 2 + q];
                        mma16816(d, ah[fm], &bh[p][q * 2]);
                        mma16816(d, ah[fm], &bl[p][q * 2]);
                        mma16816(d, al[fm], &bh[p][q * 2]);
                    }
        }
        CP_WAIT0();
        __syncthreads();
    }

    // ---- epilogue: accum -> smem fp32 (pitch 132), then RoPE/scatter ----
    float* S = (float*)dyn_smem;
    const int er = lane >> 2, ec = (lane & 3) << 1;
#pragma unroll
    for (int fm = 0; fm < 4; fm++)
#pragma unroll
        for (int fn = 0; fn < 4; fn++) {
            const int r0 = wm * 64 + fm * 16 + er;
            const int c0 = wn * 32 + fn * 8 + ec;
            S[r0 * 132 + c0] = acc[fm][fn][0];
            S[r0 * 132 + c0 + 1] = acc[fm][fn][1];
            S[(r0 + 8) * 132 + c0] = acc[fm][fn][2];
            S[(r0 + 8) * 132 + c0 + 1] = acc[fm][fn][3];
        }
    __syncthreads();

    const int r = tid >> 1, t2 = tid & 1;
    const int m = m0 + r;
    if (MODE == 0) {
        const int h = n0 / 384;
        const int sub = (n0 % 384) >> 7;          // 0=q,1=k,2=v
        const int b = m >> 11, s = m & 2047;
        float* dst = ((sub == 0) ? g_Q : (sub == 1 ? g_K : g_V))
                     + ((size_t)(b * H_ + h) * S_ + s) * HD_;
        if (sub == 2) {
            const int cbase = t2 * 64;
#pragma unroll
            for (int q4 = 0; q4 < 16; q4++) {
                float4 w = *(const float4*)(S + r * 132 + cbase + q4 * 4);
                *(float4*)(dst + cbase + q4 * 4) = w;
            }
        } else {
            const float* crow = cs + (size_t)s * HD_;
            const float* srow = sn + (size_t)s * HD_;
            const int cbase = t2 * 32;
#pragma unroll
            for (int q4 = 0; q4 < 8; q4++) {
                const int cA = cbase + q4 * 4;
                const int cB = cA + 64;
                float4 xa = *(const float4*)(S + r * 132 + cA);
                float4 xb = *(const float4*)(S + r * 132 + cB);
                float4 ca = *(const float4*)(crow + cA);
                float4 sa = *(const float4*)(srow + cA);
                float4 cb = *(const float4*)(crow + cB);
                float4 sb = *(const float4*)(srow + cB);
                float4 oa = make_float4(xa.x * ca.x - xb.x * sa.x, xa.y * ca.y - xb.y * sa.y,
                                        xa.z * ca.z - xb.z * sa.z, xa.w * ca.w - xb.w * sa.w);
                float4 ob = make_float4(xb.x * cb.x + xa.x * sb.x, xb.y * cb.y + xa.y * sb.y,
                                        xb.z * cb.z + xa.z * sb.z, xb.w * cb.w + xa.w * sb.w);
                *(float4*)(dst + cA) = oa;
                *(float4*)(dst + cB) = ob;
            }
        }
    } else {
        float* dst = out + (size_t)m * D_ + n0;
        const int cbase = t2 * 64;
#pragma unroll
        for (int q4 = 0; q4 < 16; q4++) {
            float4 w = *(const float4*)(S + r * 132 + cbase + q4 * 4);
            *(float4*)(dst + cbase + q4 * 4) = w;
        }
    }
}

// ---------------------------------------------------------------------------
// Causal flash attention, fp32 f32x2, 64x64 tiles. Epilogue emits bf16 hi/lo.
// ---------------------------------------------------------------------------
#define SPAD 65
#define ATTN_SMEM_FLOATS (64*128 + 64*128 + 64*128 + 64*SPAD)
#define ATTN_SMEM_BYTES  (ATTN_SMEM_FLOATS * 4)

__global__ void __launch_bounds__(256, 1) attn_kernel()
{
    extern __shared__ float sm[];
    float* Qs = sm;
    float* Ks = Qs + 64 * 128;
    float* Vs = Ks + 64 * 128;
    float* Ss = Vs + 64 * 128;

    const int tid = threadIdx.x;
    const int tx = tid & 15, ty = tid >> 4;
    const int qt = blockIdx.x, h = blockIdx.y, b = blockIdx.z;
    const size_t base = (size_t)(b * H_ + h) * S_ * HD_;
    const int qg0 = qt << 6;
    const float scale = 0.08838834764831845f;

#pragma unroll
    for (int i = 0; i < 8; i++) {
        const int idx4 = i * 256 + tid;
        const int row = idx4 >> 5, c4 = idx4 & 31;
        float4 v = *(const float4*)(g_Q + base + (size_t)(qg0 + row) * HD_ + (c4 << 2));
        *(float4*)(Qs + row * 128 + (c4 << 2)) = v;
    }

    float mrun[4], lrun[4];
#pragma unroll
    for (int i = 0; i < 4; i++) { mrun[i] = -1e30f; lrun[i] = 0.f; }

    u64 o2[4][4];
    const u64 z = pack2(0.f, 0.f);
#pragma unroll
    for (int i = 0; i < 4; i++)
#pragma unroll
        for (int j = 0; j < 4; j++) o2[i][j] = z;

    __syncthreads();

    for (int kt = 0; kt <= qt; kt++) {
        const int kg0 = kt << 6;
#pragma unroll
        for (int i = 0; i < 8; i++) {
            const int idx4 = i * 256 + tid;
            const int row = idx4 >> 5, c4 = idx4 & 31;
            const size_t goff = base + (size_t)(kg0 + row) * HD_ + (c4 << 2);
            float4 kv = *(const float4*)(g_K + goff);
            const int kc4 = c4 ^ ((row >> 2) & 7);
            *(float4*)(Ks + row * 128 + (kc4 << 2)) = kv;
            float4 vv = *(const float4*)(g_V + goff);
            *(float4*)(Vs + row * 128 + (c4 << 2)) = vv;
        }
        __syncthreads();

        u64 sc2[4][4];
#pragma unroll
        for (int i = 0; i < 4; i++)
#pragma unroll
            for (int j = 0; j < 4; j++) sc2[i][j] = z;

        const int ksw = tx & 7;
        for (int e4 = 0; e4 < 128; e4 += 4) {
            ulonglong2 q[4], k[4];
#pragma unroll
            for (int i = 0; i < 4; i++)
                q[i] = *(const ulonglong2*)(Qs + ((ty << 2) + i) * 128 + e4);
            const int kc = (((e4 >> 2) ^ ksw) << 2);
#pragma unroll
            for (int j = 0; j < 4; j++)
                k[j] = *(const ulonglong2*)(Ks + ((tx << 2) + j) * 128 + kc);
#pragma unroll
            for (int i = 0; i < 4; i++)
#pragma unroll
                for (int j = 0; j < 4; j++) {
                    sc2[i][j] = fma2(q[i].x, k[j].x, sc2[i][j]);
                    sc2[i][j] = fma2(q[i].y, k[j].y, sc2[i][j]);
                }
        }

        float sc[4][4];
        const bool diag = (kt == qt);
#pragma unroll
        for (int i = 0; i < 4; i++)
#pragma unroll
            for (int j = 0; j < 4; j++) {
                float2 p = unpack2(sc2[i][j]);
                float v = (p.x + p.y) * scale;
                if (diag && ((kg0 + (tx << 2) + j) > (qg0 + (ty << 2) + i))) v = -1e30f;
                sc[i][j] = v;
            }

        float alpha[4];
#pragma unroll
        for (int i = 0; i < 4; i++) {
            float mx = fmaxf(fmaxf(sc[i][0], sc[i][1]), fmaxf(sc[i][2], sc[i][3]));
#pragma unroll
            for (int off = 8; off >= 1; off >>= 1)
                mx = fmaxf(mx, __shfl_xor_sync(0xffffffffu, mx, off));
            const float mnew = fmaxf(mrun[i], mx);
            alpha[i] = __expf(mrun[i] - mnew);
            float s0 = 0.f;
#pragma unroll
            for (int j = 0; j < 4; j++) {
                const float p = __expf(sc[i][j] - mnew);
                sc[i][j] = p;
                s0 += p;
            }
#pragma unroll
            for (int off = 8; off >= 1; off >>= 1)
                s0 += __shfl_xor_sync(0xffffffffu, s0, off);
            lrun[i] = lrun[i] * alpha[i] + s0;
            mrun[i] = mnew;
#pragma unroll
            for (int j = 0; j < 4; j++)
                Ss[((ty << 2) + i) * SPAD + (tx << 2) + j] = sc[i][j];
        }
        __syncthreads();

#pragma unroll
        for (int i = 0; i < 4; i++) {
            const u64 al2 = pack2(alpha[i], alpha[i]);
#pragma unroll
            for (int j = 0; j < 4; j++) o2[i][j] = mul2(o2[i][j], al2);
        }
#pragma unroll 2
        for (int c = 0; c < 64; c++) {
            ulonglong2 v0 = *(const ulonglong2*)(Vs + c * 128 + (tx << 3));
            ulonglong2 v1 = *(const ulonglong2*)(Vs + c * 128 + (tx << 3) + 4);
#pragma unroll
            for (int i = 0; i < 4; i++) {
                const float p = Ss[((ty << 2) + i) * SPAD + c];
                const u64 p2 = pack2(p, p);
                o2[i][0] = fma2(p2, v0.x, o2[i][0]);
                o2[i][1] = fma2(p2, v0.y, o2[i][1]);
                o2[i][2] = fma2(p2, v1.x, o2[i][2]);
                o2[i][3] = fma2(p2, v1.y, o2[i][3]);
            }
        }
        __syncthreads();
    }

    // Epilogue: normalize; emit bf16 hi/lo to g_AThi / g_ATlo [B*S, H*HD]
#pragma unroll
    for (int i = 0; i < 4; i++) {
        const int r = (ty << 2) + i;
        const float inv = 1.0f / lrun[i];
        const int s = qg0 + r;
        const size_t off = ((size_t)b * S_ + s) * F_ + h * HD_ + (tx << 3);
        float2 a0 = unpack2(o2[i][0]), a1 = unpack2(o2[i][1]);
        float2 a2 = unpack2(o2[i][2]), a3 = unpack2(o2[i][3]);
        float v[8] = {a0.x * inv, a0.y * inv, a1.x * inv, a1.y * inv,
                      a2.x * inv, a2.y * inv, a3.x * inv, a3.y * inv};
        u32 hw[4], lw[4];
#pragma unroll
        for (int p = 0; p < 4; p++) {
            __nv_bfloat16 h0 = __float2bfloat16(v[2*p]);
            __nv_bfloat16 h1 = __float2bfloat16(v[2*p+1]);
            __nv_bfloat16 l0 = __float2bfloat16(v[2*p] - __bfloat162float(h0));
            __nv_bfloat16 l1 = __float2bfloat16(v[2*p+1] - __bfloat162float(h1));
            hw[p] = ((u32)__bfloat16_as_ushort(h1) << 16) | __bfloat16_as_ushort(h0);
            lw[p] = ((u32)__bfloat16_as_ushort(l1) << 16) | __bfloat16_as_ushort(l0);
        }
        *(uint4*)(g_AThi + off) = make_uint4(hw[0], hw[1], hw[2], hw[3]);
        *(uint4*)(g_ATlo + off) = make_uint4(lw[0], lw[1], lw[2], lw[3]);
    }
}

// ---------------------------------------------------------------------------
extern "C" void kernel_launch(void* const* d_in, const int* in_sizes, int n_in,
                              void* d_out, int out_size)
{
    const float* hs = (const float*)d_in[0];   // hidden_states [B,S,D]
    const float* cs = (const float*)d_in[1];   // cos [S,HD]
    const float* sn = (const float*)d_in[2];   // sin [S,HD]
    const float* wq = (const float*)d_in[3];   // w_qkv flat [6144,2048]
    const float* wo = (const float*)d_in[4];   // w_o [2048,2048]
    float* out = (float*)d_out;

    cudaFuncSetAttribute(attn_kernel, cudaFuncAttributeMaxDynamicSharedMemorySize, ATTN_SMEM_BYTES);
    cudaFuncSetAttribute(mma_gemm_kernel<0>, cudaFuncAttributeMaxDynamicSharedMemorySize, MMA_SMEM_BYTES);
    cudaFuncSetAttribute(mma_gemm_kernel<1>, cudaFuncAttributeMaxDynamicSharedMemorySize, MMA_SMEM_BYTES);

    __nv_bfloat16 *ahi, *alo, *whi, *wlo, *wohi, *wolo, *athi, *atlo;
    cudaGetSymbolAddress((void**)&ahi, g_Ahi);   cudaGetSymbolAddress((void**)&alo, g_Alo);
    cudaGetSymbolAddress((void**)&whi, g_Whi);   cudaGetSymbolAddress((void**)&wlo, g_Wlo);
    cudaGetSymbolAddress((void**)&wohi, g_Wohi); cudaGetSymbolAddress((void**)&wolo, g_Wolo);
    cudaGetSymbolAddress((void**)&athi, g_AThi); cudaGetSymbolAddress((void**)&atlo, g_ATlo);

    // 1. split inputs to bf16 hi/lo
    {
        int n4 = (M_ * D_) / 4;
        split_bf16_kernel<<<(n4 + 255) / 256, 256>>>((const float4*)hs, (uint2*)ahi, (uint2*)alo, n4);
        n4 = (NQKV * D_) / 4;
        split_bf16_kernel<<<(n4 + 255) / 256, 256>>>((const float4*)wq, (uint2*)whi, (uint2*)wlo, n4);
        n4 = (D_ * F_) / 4;
        split_bf16_kernel<<<(n4 + 255) / 256, 256>>>((const float4*)wo, (uint2*)wohi, (uint2*)wolo, n4);
    }

    // 2. QKV projection (HMMA bf16x3) + RoPE -> g_Q/g_K/g_V
    mma_gemm_kernel<0><<<dim3(NQKV / 128, M_ / 128), 256, MMA_SMEM_BYTES>>>(
        ahi, alo, whi, wlo, cs, sn, nullptr);

    // 3. Causal flash attention -> g_AThi/g_ATlo (bf16 hi/lo)
    attn_kernel<<<dim3(S_ / 64, H_, B_), 256, ATTN_SMEM_BYTES>>>();

    // 4. Output projection (HMMA bf16x3) -> d_out
    mma_gemm_kernel<1><<<dim3(D_ / 128, M_ / 128), 256, MMA_SMEM_BYTES>>>(
        athi, atlo, wohi, wolo, nullptr, nullptr, out);
}

// round 5
// speedup vs baseline: 3.5214x; 1.5917x over previous
#include <cuda_runtime.h>
#include <cuda_bf16.h>
#include <cstdint>
#include <math.h>

// Problem constants
#define B_   2
#define S_   2048
#define D_   2048
#define H_   16
#define HD_  128
#define M_   (B_ * S_)     // 4096
#define F_   (H_ * HD_)    // 2048
#define NQKV (3 * F_)      // 6144

typedef unsigned long long u64;
typedef unsigned int u32;

__device__ __forceinline__ u32 smem_u32(const void* p) {
    u32 a; asm("{ .reg .u64 t; cvta.to.shared.u64 t, %1; cvt.u32.u64 %0, t; }" : "=r"(a) : "l"(p));
    return a;
}

// ---- mma.sync / ldmatrix / cp.async ----
__device__ __forceinline__ void ldsm4(u32* r, u32 addr) {
    asm volatile("ldmatrix.sync.aligned.m8n8.x4.shared.b16 {%0,%1,%2,%3}, [%4];"
        : "=r"(r[0]), "=r"(r[1]), "=r"(r[2]), "=r"(r[3]) : "r"(addr));
}
__device__ __forceinline__ void ldsm4t(u32* r, u32 addr) {
    asm volatile("ldmatrix.sync.aligned.m8n8.x4.trans.shared.b16 {%0,%1,%2,%3}, [%4];"
        : "=r"(r[0]), "=r"(r[1]), "=r"(r[2]), "=r"(r[3]) : "r"(addr));
}
__device__ __forceinline__ void mma16816(float* d, const u32* a, const u32* b) {
    asm volatile("mma.sync.aligned.m16n8k16.row.col.f32.bf16.bf16.f32 "
        "{%0,%1,%2,%3}, {%4,%5,%6,%7}, {%8,%9}, {%0,%1,%2,%3};"
        : "+f"(d[0]), "+f"(d[1]), "+f"(d[2]), "+f"(d[3])
        : "r"(a[0]), "r"(a[1]), "r"(a[2]), "r"(a[3]), "r"(b[0]), "r"(b[1]));
}
__device__ __forceinline__ void cp_async16(u32 dst, const void* src) {
    asm volatile("cp.async.cg.shared.global [%0], [%1], 16;" :: "r"(dst), "l"(src));
}
#define CP_COMMIT() asm volatile("cp.async.commit_group;" ::: "memory")
#define CP_WAIT0()  asm volatile("cp.async.wait_group 0;" ::: "memory")
#define CP_WAIT1()  asm volatile("cp.async.wait_group 1;" ::: "memory")

// split f32 pair -> packed bf16x2 hi (returned) and lo (out-param)
__device__ __forceinline__ u32 split_pack(float x, float y, u32& lo) {
    float hx = __bfloat162float(__float2bfloat16(x));
    float hy = __bfloat162float(__float2bfloat16(y));
    u32 hi;
    asm("cvt.rn.bf16x2.f32 %0, %1, %2;" : "=r"(hi) : "f"(hy), "f"(hx));
    asm("cvt.rn.bf16x2.f32 %0, %1, %2;" : "=r"(lo) : "f"(y - hy), "f"(x - hx));
    return hi;
}

// ---------------- device scratch ----------------
__device__ __nv_bfloat16 g_Qhi[(size_t)B_ * H_ * S_ * HD_], g_Qlo[(size_t)B_ * H_ * S_ * HD_];
__device__ __nv_bfloat16 g_Khi[(size_t)B_ * H_ * S_ * HD_], g_Klo[(size_t)B_ * H_ * S_ * HD_];
__device__ __nv_bfloat16 g_Vhi[(size_t)B_ * H_ * S_ * HD_], g_Vlo[(size_t)B_ * H_ * S_ * HD_];
__device__ __nv_bfloat16 g_Ahi[(size_t)M_ * D_],   g_Alo[(size_t)M_ * D_];
__device__ __nv_bfloat16 g_Whi[(size_t)NQKV * D_], g_Wlo[(size_t)NQKV * D_];
__device__ __nv_bfloat16 g_Wohi[(size_t)D_ * F_],  g_Wolo[(size_t)D_ * F_];
__device__ __nv_bfloat16 g_AThi[(size_t)M_ * F_],  g_ATlo[(size_t)M_ * F_];

// ---------------------------------------------------------------------------
// Split fp32 -> bf16 (hi, lo)
// ---------------------------------------------------------------------------
__global__ void split_bf16_kernel(const float4* __restrict__ x,
                                  uint2* __restrict__ hi, uint2* __restrict__ lo, int n4)
{
    int i = blockIdx.x * blockDim.x + threadIdx.x;
    if (i >= n4) return;
    float4 v = x[i];
    u32 l0, l1, h0, h1;
    h0 = split_pack(v.x, v.y, l0);
    h1 = split_pack(v.z, v.w, l1);
    hi[i] = make_uint2(h0, h1);
    lo[i] = make_uint2(l0, l1);
}

// ---------------------------------------------------------------------------
// bf16x3 GEMM via mma.sync m16n8k16. Tile 128x128, K=2048, chunks of 64.
// MODE 0: QKV + RoPE -> Q/K/V bf16 hi/lo.  MODE 1: out proj -> fp32 out.
// ---------------------------------------------------------------------------
#define NCHUNK 32
#define TILEB 16384
#define STAGEB (4 * TILEB)
#define MMA_SMEM_BYTES (2 * STAGEB)

__device__ __forceinline__ u32 swz(u32 row, u32 cb) {
    return row * 128u + (cb ^ ((row & 7u) << 4));
}

template <int MODE>
__global__ void __launch_bounds__(256, 1) mma_gemm_kernel(
    const __nv_bfloat16* __restrict__ Ahi, const __nv_bfloat16* __restrict__ Alo,
    const __nv_bfloat16* __restrict__ Bhi, const __nv_bfloat16* __restrict__ Blo,
    const float* __restrict__ cs, const float* __restrict__ sn,
    float* __restrict__ out)
{
    extern __shared__ char dyn_smem[];
    const u32 smb = smem_u32(dyn_smem);

    const int tid = threadIdx.x;
    const int wid = tid >> 5;
    const int lane = tid & 31;
    const int wm = wid >> 2, wn = wid & 3;
    const int m0 = blockIdx.y << 7;
    const int n0 = blockIdx.x << 7;

    const __nv_bfloat16* srcOp[4] = {Ahi, Alo, Bhi, Blo};
    const int rowOff[4] = {m0, m0, n0, n0};

    {
#pragma unroll
        for (int op = 0; op < 4; op++) {
#pragma unroll
            for (int rep = 0; rep < 4; rep++) {
                int lin = rep * 256 + tid;
                int row = lin >> 3, u = lin & 7;
                cp_async16(smb + op * TILEB + swz(row, u * 16),
                           srcOp[op] + (size_t)(rowOff[op] + row) * 2048 + u * 8);
            }
        }
        CP_COMMIT(); CP_WAIT0();
    }
    __syncthreads();

    const u32 aRow = (u32)(wm * 64 + (lane & 15));
    const u32 aSw = (aRow & 7u) << 4;
    const u32 aColSel = (u32)((lane >> 4) << 4);
    u32 aOff[4];
#pragma unroll
    for (int fm = 0; fm < 4; fm++) aOff[fm] = (aRow + fm * 16) * 128u;

    u32 bOff[2], bSw[2];
#pragma unroll
    for (int p = 0; p < 2; p++) {
        u32 brow = (u32)(wn * 32 + p * 16 + ((lane >> 4) << 3) + (lane & 7));
        bOff[p] = brow * 128u;
        bSw[p] = (brow & 7u) << 4;
    }
    const u32 bColSel = (u32)(((lane >> 3) & 1) << 4);

    float acc[4][4][4];
#pragma unroll
    for (int i = 0; i < 4; i++)
#pragma unroll
        for (int j = 0; j < 4; j++)
#pragma unroll
            for (int q = 0; q < 4; q++) acc[i][j][q] = 0.f;

    for (int c = 0; c < NCHUNK; c++) {
        const u32 stage = smb + (u32)(c & 1) * STAGEB;
        if (c + 1 < NCHUNK) {
            const int k0 = (c + 1) * 64;
            const u32 nst = smb + (u32)((c + 1) & 1) * STAGEB;
#pragma unroll
            for (int op = 0; op < 4; op++) {
#pragma unroll
                for (int rep = 0; rep < 4; rep++) {
                    int lin = rep * 256 + tid;
                    int row = lin >> 3, u = lin & 7;
                    cp_async16(nst + op * TILEB + swz(row, u * 16),
                               srcOp[op] + (size_t)(rowOff[op] + row) * 2048 + k0 + u * 8);
                }
            }
            CP_COMMIT();
        }
#pragma unroll
        for (int ks = 0; ks < 4; ks++) {
            const u32 cbA = (u32)(ks * 32) + aColSel;
            const u32 cbB = (u32)(ks * 32) + bColSel;
            u32 ah[4][4], al[4][4];
#pragma unroll
            for (int fm = 0; fm < 4; fm++) {
                ldsm4(ah[fm], stage + aOff[fm] + (cbA ^ aSw));
                ldsm4(al[fm], stage + TILEB + aOff[fm] + (cbA ^ aSw));
            }
            u32 bh[2][4], bl[2][4];
#pragma unroll
            for (int p = 0; p < 2; p++) {
                ldsm4(bh[p], stage + 2 * TILEB + bOff[p] + (cbB ^ bSw[p]));
                ldsm4(bl[p], stage + 3 * TILEB + bOff[p] + (cbB ^ bSw[p]));
            }
#pragma unroll
            for (int fm = 0; fm < 4; fm++)
#pragma unroll
                for (int p = 0; p < 2; p++)
#pragma unroll
                    for (int q = 0; q < 2; q++) {
                        float* d = acc[fm][p * 2 + q];
                        mma16816(d, ah[fm], &bh[p][q * 2]);
                        mma16816(d, ah[fm], &bl[p][q * 2]);
                        mma16816(d, al[fm], &bh[p][q * 2]);
                    }
        }
        CP_WAIT0();
        __syncthreads();
    }

    // epilogue: accum -> smem fp32 (pitch 132), then scatter
    float* S = (float*)dyn_smem;
    const int er = lane >> 2, ec = (lane & 3) << 1;
#pragma unroll
    for (int fm = 0; fm < 4; fm++)
#pragma unroll
        for (int fn = 0; fn < 4; fn++) {
            const int r0 = wm * 64 + fm * 16 + er;
            const int c0 = wn * 32 + fn * 8 + ec;
            S[r0 * 132 + c0] = acc[fm][fn][0];
            S[r0 * 132 + c0 + 1] = acc[fm][fn][1];
            S[(r0 + 8) * 132 + c0] = acc[fm][fn][2];
            S[(r0 + 8) * 132 + c0 + 1] = acc[fm][fn][3];
        }
    __syncthreads();

    const int r = tid >> 1, t2 = tid & 1;
    const int m = m0 + r;
    if (MODE == 0) {
        const int h = n0 / 384;
        const int sub = (n0 % 384) >> 7;          // 0=q,1=k,2=v
        const int b = m >> 11, s = m & 2047;
        const size_t doff = ((size_t)(b * H_ + h) * S_ + s) * HD_;
        if (sub == 2) {
            const int cb = t2 * 64;
#pragma unroll
            for (int g = 0; g < 8; g++) {
                u32 hw[4], lw[4];
#pragma unroll
                for (int p = 0; p < 4; p++) {
                    float x = S[r * 132 + cb + g * 8 + p * 2];
                    float y = S[r * 132 + cb + g * 8 + p * 2 + 1];
                    hw[p] = split_pack(x, y, lw[p]);
                }
                *(uint4*)(g_Vhi + doff + cb + g * 8) = make_uint4(hw[0], hw[1], hw[2], hw[3]);
                *(uint4*)(g_Vlo + doff + cb + g * 8) = make_uint4(lw[0], lw[1], lw[2], lw[3]);
            }
        } else {
            const float scl = (sub == 0) ? 0.08838834764831845f : 1.0f;  // fold 1/sqrt(HD) into Q
            __nv_bfloat16* dhi = (sub == 0) ? g_Qhi : g_Khi;
            __nv_bfloat16* dlo = (sub == 0) ? g_Qlo : g_Klo;
            const float* crow = cs + (size_t)s * HD_;
            const float* srow = sn + (size_t)s * HD_;
#pragma unroll
            for (int g = 0; g < 4; g++) {
                const int cA = t2 * 32 + g * 8;
                const int cB = cA + 64;
                u32 hA[4], lA[4], hB[4], lB[4];
#pragma unroll
                for (int p = 0; p < 4; p++) {
                    const int c0 = cA + p * 2, c1 = cA + p * 2 + 1;
                    float xa0 = S[r * 132 + c0], xa1 = S[r * 132 + c1];
                    float xb0 = S[r * 132 + c0 + 64], xb1 = S[r * 132 + c1 + 64];
                    float oa0 = (xa0 * crow[c0] - xb0 * srow[c0]) * scl;
                    float oa1 = (xa1 * crow[c1] - xb1 * srow[c1]) * scl;
                    float ob0 = (xb0 * crow[c0 + 64] + xa0 * srow[c0 + 64]) * scl;
                    float ob1 = (xb1 * crow[c1 + 64] + xa1 * srow[c1 + 64]) * scl;
                    hA[p] = split_pack(oa0, oa1, lA[p]);
                    hB[p] = split_pack(ob0, ob1, lB[p]);
                }
                *(uint4*)(dhi + doff + cA) = make_uint4(hA[0], hA[1], hA[2], hA[3]);
                *(uint4*)(dlo + doff + cA) = make_uint4(lA[0], lA[1], lA[2], lA[3]);
                *(uint4*)(dhi + doff + cB) = make_uint4(hB[0], hB[1], hB[2], hB[3]);
                *(uint4*)(dlo + doff + cB) = make_uint4(lB[0], lB[1], lB[2], lB[3]);
            }
        }
    } else {
        float* dst = out + (size_t)m * D_ + n0;
        const int cbase = t2 * 64;
#pragma unroll
        for (int q4 = 0; q4 < 16; q4++) {
            float4 w = *(const float4*)(S + r * 132 + cbase + q4 * 4);
            *(float4*)(dst + cbase + q4 * 4) = w;
        }
    }
}

// ---------------------------------------------------------------------------
// Tensor-core causal flash attention. CTA = 128 q rows x (b,h); 8 warps of
// 16 rows. kt tiles of 64 keys, double-buffered K/V hi/lo via cp.async.
// QK = bf16x3, PV = bf16x3 with P split hi/lo in registers.
// SMEM: Qhi 32K | Qlo 32K | stage0 64K | stage1 64K = 192KB.
// ---------------------------------------------------------------------------
#define ATT_SMEM_BYTES (192 * 1024)
#define AQLO 32768
#define ASTG 65536
#define AKLO 16384
#define AVHI 32768
#define AVLO 49152

__device__ __forceinline__ u32 aswz(u32 row, u32 cb) {   // 256B-pitch rows
    return row * 256u + (cb ^ ((row & 7u) << 4));
}

__global__ void __launch_bounds__(256, 1) attn_mma_kernel()
{
    extern __shared__ char dyn_smem[];
    const u32 smb = smem_u32(dyn_smem);
    const int tid = threadIdx.x, wid = tid >> 5, lane = tid & 31;
    const int qt = blockIdx.x, h = blockIdx.y, b = blockIdx.z;
    const int qg0 = qt << 7;
    const size_t bh = (size_t)(b * H_ + h) * S_;

    // prologue: Q hi/lo async (group 1)
    {
        const __nv_bfloat16* qh = g_Qhi + (bh + qg0) * HD_;
        const __nv_bfloat16* ql = g_Qlo + (bh + qg0) * HD_;
#pragma unroll
        for (int rep = 0; rep < 8; rep++) {
            int lin = rep * 256 + tid;
            int row = lin >> 4, u = lin & 15;
            u32 so = aswz(row, u * 16);
            cp_async16(smb + so, qh + (size_t)row * HD_ + u * 8);
            cp_async16(smb + AQLO + so, ql + (size_t)row * HD_ + u * 8);
        }
        CP_COMMIT();
    }

    const __nv_bfloat16* khg = g_Khi + bh * HD_;
    const __nv_bfloat16* klg = g_Klo + bh * HD_;
    const __nv_bfloat16* vhg = g_Vhi + bh * HD_;
    const __nv_bfloat16* vlg = g_Vlo + bh * HD_;

    // stage loader (4 tiles of 64x128 bf16)
    auto load_stage = [&](int st, int kg0) {
        const u32 dst = smb + ASTG + (u32)st * ASTG;
        const __nv_bfloat16* srcs[4] = {khg + (size_t)kg0 * HD_, klg + (size_t)kg0 * HD_,
                                        vhg + (size_t)kg0 * HD_, vlg + (size_t)kg0 * HD_};
#pragma unroll
        for (int op = 0; op < 4; op++) {
#pragma unroll
            for (int rep = 0; rep < 4; rep++) {
                int lin = rep * 256 + tid;
                int row = lin >> 4, u = lin & 15;
                cp_async16(dst + op * 16384 + aswz(row, u * 16),
                           srcs[op] + (size_t)row * HD_ + u * 8);
            }
        }
    };

    const int nkt = 2 * qt + 2;
    load_stage(0, 0);
    CP_COMMIT();

    // fragment addressing
    const u32 aRow = (u32)(wid * 16 + (lane & 15));
    const u32 aSw = (aRow & 7u) << 4;
    const u32 aCol = (u32)((lane >> 4) << 4);
    const u32 aBase = aRow * 256u;
    const u32 kRow = (u32)(((lane >> 4) << 3) + (lane & 7));   // + p*16
    const u32 kSw = (u32)((lane & 7) << 4);
    const u32 kColT = (u32)(((lane >> 3) & 1) << 4);
    const u32 vRow = (u32)(lane & 15);                          // + j*16
    const u32 vColT = (u32)((lane >> 4) << 4);

    u32 qhf[8][4], qlf[8][4];
    float o[16][4];
#pragma unroll
    for (int f = 0; f < 16; f++)
#pragma unroll
        for (int q = 0; q < 4; q++) o[f][q] = 0.f;
    float m0r = -1e30f, m1r = -1e30f, l0 = 0.f, l1 = 0.f;

    for (int kt = 0; kt < nkt; kt++) {
        if (kt + 1 < nkt) {
            load_stage((kt + 1) & 1, (kt + 1) * 64);
            CP_COMMIT();
            CP_WAIT1();
        } else {
            CP_WAIT0();
        }
        __syncthreads();
        if (kt == 0) {
#pragma unroll
            for (int ks = 0; ks < 8; ks++) {
                u32 qa = smb + aBase + (((u32)(ks * 32) + aCol) ^ aSw);
                ldsm4(qhf[ks], qa);
                ldsm4(qlf[ks], qa + AQLO);
            }
        }
        const int kg0 = kt * 64;
        const bool skip = kg0 > qg0 + wid * 16 + 15;
        if (!skip) {
            const u32 stg = smb + ASTG + (u32)(kt & 1) * ASTG;
            float s[8][4];
#pragma unroll
            for (int f = 0; f < 8; f++)
#pragma unroll
                for (int q = 0; q < 4; q++) s[f][q] = 0.f;

            // QK^T (bf16x3)
#pragma unroll
            for (int ks = 0; ks < 8; ks++) {
#pragma unroll
                for (int p = 0; p < 4; p++) {
                    u32 addr = stg + (u32)(p * 16 + kRow) * 256u + (((u32)(ks * 32) + kColT) ^ kSw);
                    u32 kh4[4], kl4[4];
                    ldsm4(kh4, addr);
                    ldsm4(kl4, addr + AKLO);
                    mma16816(s[2 * p], qhf[ks], &kh4[0]);
                    mma16816(s[2 * p], qhf[ks], &kl4[0]);
                    mma16816(s[2 * p], qlf[ks], &kh4[0]);
                    mma16816(s[2 * p + 1], qhf[ks], &kh4[2]);
                    mma16816(s[2 * p + 1], qhf[ks], &kl4[2]);
                    mma16816(s[2 * p + 1], qlf[ks], &kh4[2]);
                }
            }

            // causal mask
            const int row0 = qg0 + wid * 16 + (lane >> 2);
            if (kg0 + 63 > qg0 + wid * 16) {
#pragma unroll
                for (int f = 0; f < 8; f++) {
                    const int col = kg0 + f * 8 + (lane & 3) * 2;
                    if (col > row0)     s[f][0] = -1e30f;
                    if (col + 1 > row0) s[f][1] = -1e30f;
                    if (col > row0 + 8)     s[f][2] = -1e30f;
                    if (col + 1 > row0 + 8) s[f][3] = -1e30f;
                }
            }

            // online softmax (rows r=row0 and r+8)
            float mx0 = -1e30f, mx1 = -1e30f;
#pragma unroll
            for (int f = 0; f < 8; f++) {
                mx0 = fmaxf(mx0, fmaxf(s[f][0], s[f][1]));
                mx1 = fmaxf(mx1, fmaxf(s[f][2], s[f][3]));
            }
            mx0 = fmaxf(mx0, __shfl_xor_sync(0xffffffffu, mx0, 1));
            mx0 = fmaxf(mx0, __shfl_xor_sync(0xffffffffu, mx0, 2));
            mx1 = fmaxf(mx1, __shfl_xor_sync(0xffffffffu, mx1, 1));
            mx1 = fmaxf(mx1, __shfl_xor_sync(0xffffffffu, mx1, 2));
            const float mn0 = fmaxf(m0r, mx0), mn1 = fmaxf(m1r, mx1);
            const float al0 = __expf(m0r - mn0), al1 = __expf(m1r - mn1);
            m0r = mn0; m1r = mn1;
            float s0 = 0.f, s1 = 0.f;
#pragma unroll
            for (int f = 0; f < 8; f++) {
                s[f][0] = __expf(s[f][0] - mn0);
                s[f][1] = __expf(s[f][1] - mn0);
                s[f][2] = __expf(s[f][2] - mn1);
                s[f][3] = __expf(s[f][3] - mn1);
                s0 += s[f][0] + s[f][1];
                s1 += s[f][2] + s[f][3];
            }
            s0 += __shfl_xor_sync(0xffffffffu, s0, 1);
            s0 += __shfl_xor_sync(0xffffffffu, s0, 2);
            s1 += __shfl_xor_sync(0xffffffffu, s1, 1);
            s1 += __shfl_xor_sync(0xffffffffu, s1, 2);
            l0 = l0 * al0 + s0;
            l1 = l1 * al1 + s1;
#pragma unroll
            for (int f = 0; f < 16; f++) {
                o[f][0] *= al0; o[f][1] *= al0;
                o[f][2] *= al1; o[f][3] *= al1;
            }

            // P -> A-frags (hi/lo), pure register packing
            u32 ph[4][4], pl[4][4];
#pragma unroll
            for (int j = 0; j < 4; j++) {
                ph[j][0] = split_pack(s[2 * j][0], s[2 * j][1], pl[j][0]);
                ph[j][1] = split_pack(s[2 * j][2], s[2 * j][3], pl[j][1]);
                ph[j][2] = split_pack(s[2 * j + 1][0], s[2 * j + 1][1], pl[j][2]);
                ph[j][3] = split_pack(s[2 * j + 1][2], s[2 * j + 1][3], pl[j][3]);
            }

            // PV (bf16x3), V^T frags via ldmatrix.trans
#pragma unroll
            for (int j = 0; j < 4; j++) {
#pragma unroll
                for (int ep = 0; ep < 8; ep++) {
                    u32 va = stg + AVHI + (u32)(j * 16 + vRow) * 256u + (((u32)(ep * 32) + vColT) ^ kSw);
                    u32 vh4[4], vl4[4];
                    ldsm4t(vh4, va);
                    ldsm4t(vl4, va + 16384);
                    mma16816(o[2 * ep], ph[j], &vh4[0]);
                    mma16816(o[2 * ep], ph[j], &vl4[0]);
                    mma16816(o[2 * ep], pl[j], &vh4[0]);
                    mma16816(o[2 * ep + 1], ph[j], &vh4[2]);
                    mma16816(o[2 * ep + 1], ph[j], &vl4[2]);
                    mma16816(o[2 * ep + 1], pl[j], &vh4[2]);
                }
            }
        }
        __syncthreads();
    }

    // epilogue: normalize, split to bf16 hi/lo, store
    const float inv0 = 1.0f / l0, inv1 = 1.0f / l1;
    const int srow0 = qg0 + wid * 16 + (lane >> 2);
    const size_t ro0 = ((size_t)b * S_ + srow0) * F_ + h * HD_;
    const size_t ro1 = ro0 + (size_t)8 * F_;
#pragma unroll
    for (int f = 0; f < 16; f++) {
        const int e = f * 8 + (lane & 3) * 2;
        u32 lo0, lo1;
        u32 hi0 = split_pack(o[f][0] * inv0, o[f][1] * inv0, lo0);
        u32 hi1 = split_pack(o[f][2] * inv1, o[f][3] * inv1, lo1);
        *(u32*)(g_AThi + ro0 + e) = hi0;
        *(u32*)(g_ATlo + ro0 + e) = lo0;
        *(u32*)(g_AThi + ro1 + e) = hi1;
        *(u32*)(g_ATlo + ro1 + e) = lo1;
    }
}

// ---------------------------------------------------------------------------
extern "C" void kernel_launch(void* const* d_in, const int* in_sizes, int n_in,
                              void* d_out, int out_size)
{
    const float* hs = (const float*)d_in[0];   // hidden_states [B,S,D]
    const float* cs = (const float*)d_in[1];   // cos [S,HD]
    const float* sn = (const float*)d_in[2];   // sin [S,HD]
    const float* wq = (const float*)d_in[3];   // w_qkv flat [6144,2048]
    const float* wo = (const float*)d_in[4];   // w_o [2048,2048]
    float* out = (float*)d_out;

    cudaFuncSetAttribute(mma_gemm_kernel<0>, cudaFuncAttributeMaxDynamicSharedMemorySize, MMA_SMEM_BYTES);
    cudaFuncSetAttribute(mma_gemm_kernel<1>, cudaFuncAttributeMaxDynamicSharedMemorySize, MMA_SMEM_BYTES);
    cudaFuncSetAttribute(attn_mma_kernel, cudaFuncAttributeMaxDynamicSharedMemorySize, ATT_SMEM_BYTES);

    __nv_bfloat16 *ahi, *alo, *whi, *wlo, *wohi, *wolo, *athi, *atlo;
    cudaGetSymbolAddress((void**)&ahi, g_Ahi);   cudaGetSymbolAddress((void**)&alo, g_Alo);
    cudaGetSymbolAddress((void**)&whi, g_Whi);   cudaGetSymbolAddress((void**)&wlo, g_Wlo);
    cudaGetSymbolAddress((void**)&wohi, g_Wohi); cudaGetSymbolAddress((void**)&wolo, g_Wolo);
    cudaGetSymbolAddress((void**)&athi, g_AThi); cudaGetSymbolAddress((void**)&atlo, g_ATlo);

    // 1. split inputs to bf16 hi/lo
    {
        int n4 = (M_ * D_) / 4;
        split_bf16_kernel<<<(n4 + 255) / 256, 256>>>((const float4*)hs, (uint2*)ahi, (uint2*)alo, n4);
        n4 = (NQKV * D_) / 4;
        split_bf16_kernel<<<(n4 + 255) / 256, 256>>>((const float4*)wq, (uint2*)whi, (uint2*)wlo, n4);
        n4 = (D_ * F_) / 4;
        split_bf16_kernel<<<(n4 + 255) / 256, 256>>>((const float4*)wo, (uint2*)wohi, (uint2*)wolo, n4);
    }

    // 2. QKV projection (HMMA bf16x3) + RoPE -> Q/K/V bf16 hi/lo
    mma_gemm_kernel<0><<<dim3(NQKV / 128, M_ / 128), 256, MMA_SMEM_BYTES>>>(
        ahi, alo, whi, wlo, cs, sn, nullptr);

    // 3. Tensor-core causal flash attention -> g_AThi/g_ATlo
    attn_mma_kernel<<<dim3(S_ / 128, H_, B_), 256, ATT_SMEM_BYTES>>>();

    // 4. Output projection (HMMA bf16x3) -> d_out
    mma_gemm_kernel<1><<<dim3(D_ / 128, M_ / 128), 256, MMA_SMEM_BYTES>>>(
        athi, atlo, wohi, wolo, nullptr, nullptr, out);
}